// round 5
// baseline (speedup 1.0000x reference)
#include <cuda_runtime.h>
#include <cuda_fp16.h>
#include <math.h>
#include <stdint.h>

// ---------------- problem constants ----------------
constexpr int B_  = 32;
constexpr int S_  = 576;
constexpr int E_  = 768;
constexpr int H_  = 12;
constexpr int D_  = 64;
constexpr int BS_ = B_ * S_;                    // 18432
constexpr long OUT1  = (long)BS_ * E_;          // 14,155,776
constexpr long NATTN = (long)B_ * H_ * S_ * S_; // 127,401,984
constexpr float SCALE_ = 0.125f;
constexpr long MPL = (long)BS_ * E_;            // activation plane elems
constexpr long WPL = (long)E_ * E_;             // weight plane elems

// ---------------- device scratch: hi plane at [0,n), lo plane at [n,2n) ----
__device__ __half g_hs [2 * MPL];
__device__ __half g_qw [2 * WPL];
__device__ __half g_kw [2 * WPL];
__device__ __half g_vw [2 * WPL];
__device__ __half g_ow [2 * WPL];
__device__ __half g_q  [2 * MPL];   // [B,H,S,D], pre-scaled by 0.125
__device__ __half g_k  [2 * MPL];   // [B,H,S,D]
__device__ __half g_v  [2 * MPL];   // [B,H,D,S] (transposed)
__device__ __half g_ctx[2 * MPL];   // [B*S, E]
__device__ float  g_attn[(size_t)NATTN];

// ---------------- helpers ----------------
__device__ __forceinline__ uint32_t smem_u32(const void* p) {
    uint32_t a;
    asm("{ .reg .u64 t; cvta.to.shared.u64 t, %1; cvt.u32.u64 %0, t; }" : "=r"(a) : "l"(p));
    return a;
}
__device__ __forceinline__ void cp16(uint32_t saddr, const void* gaddr) {
    asm volatile("cp.async.cg.shared.global [%0], [%1], 16;" :: "r"(saddr), "l"(gaddr));
}
#define CP_COMMIT() asm volatile("cp.async.commit_group;" ::: "memory")
template<int N> __device__ __forceinline__ void cp_wait() {
    asm volatile("cp.async.wait_group %0;" :: "n"(N) : "memory");
}
__device__ __forceinline__ unsigned u32h2(__half a, __half b) {
    return (unsigned)__half_as_ushort(a) | ((unsigned)__half_as_ushort(b) << 16);
}
__device__ __forceinline__ unsigned ph2(float a, float b) {
    return u32h2(__float2half_rn(a), __float2half_rn(b));
}
__device__ __forceinline__ unsigned pl2(float a, float b) {
    __half ha = __float2half_rn(a), hb = __float2half_rn(b);
    return u32h2(__float2half_rn(a - __half2float(ha)),
                 __float2half_rn(b - __half2float(hb)));
}
__device__ __forceinline__ void ldsm4(unsigned* r, uint32_t addr) {
    asm volatile("ldmatrix.sync.aligned.m8n8.x4.shared.b16 {%0,%1,%2,%3}, [%4];"
                 : "=r"(r[0]), "=r"(r[1]), "=r"(r[2]), "=r"(r[3]) : "r"(addr));
}
__device__ __forceinline__ void mma16816(float* d, const unsigned* a, const unsigned* b) {
    asm volatile(
        "mma.sync.aligned.m16n8k16.row.col.f32.f16.f16.f32 "
        "{%0,%1,%2,%3}, {%4,%5,%6,%7}, {%8,%9}, {%0,%1,%2,%3};"
        : "+f"(d[0]), "+f"(d[1]), "+f"(d[2]), "+f"(d[3])
        : "r"(a[0]), "r"(a[1]), "r"(a[2]), "r"(a[3]), "r"(b[0]), "r"(b[1]));
}

// ---------------- pack fp32 -> hi/lo fp16 planes ----------------
__global__ void pack_split(const float* __restrict__ src, __half* __restrict__ dhi, long n) {
    __half* dlo = dhi + n;
    const long stride = (long)gridDim.x * blockDim.x * 2;
    for (long i = ((long)blockIdx.x * blockDim.x + threadIdx.x) * 2; i < n; i += stride) {
        float2 f = *(const float2*)(src + i);
        __half h0 = __float2half_rn(f.x), h1 = __float2half_rn(f.y);
        __half l0 = __float2half_rn(f.x - __half2float(h0));
        __half l1 = __float2half_rn(f.y - __half2float(h1));
        *(unsigned*)(dhi + i) = u32h2(h0, h1);
        *(unsigned*)(dlo + i) = u32h2(l0, l1);
    }
}

// ============================================================================
// Projection GEMM core: 128x64 block, 8 warps (32x32), BK=32, fp16 3-pass,
// 3-stage cp.async ring, one __syncthreads per chunk. K = 768 (NC = 24).
// ============================================================================
constexpr int LDS_  = 40;               // halfs per smem row
constexpr int PA_L  = 128 * LDS_;       // 5120
constexpr int PB_H  = 2 * PA_L;         // 10240
constexpr int PB_L  = PB_H + 64 * LDS_; // 12800
constexpr int PSTG  = PB_L + 64 * LDS_; // 15360 halfs per stage
constexpr int PSMEM = 3 * PSTG * 2;     // 92160 bytes

__device__ __forceinline__ void proj_main(
    const __half* __restrict__ Ahi, const __half* __restrict__ Bhi,
    long APL, long BPL, int bm, int bn, int tid, int lane,
    int warp_m, int warp_n, uint32_t sbase, float acc[2][4][4])
{
    auto issue = [&](int c) {
        if (c < 24) {
            const uint32_t st = sbase + (uint32_t)((c % 3) * PSTG) * 2;
            const int k0 = c * 32;
            #pragma unroll
            for (int i = 0; i < 6; i++) {
                const int idx = tid + i * 256;
                const int q = idx & 3;
                if (idx < 512) {
                    const int r = idx >> 2;
                    cp16(st + (r * LDS_ + q * 8) * 2, Ahi + (long)(bm + r) * E_ + k0 + q * 8);
                } else if (idx < 1024) {
                    const int r = (idx - 512) >> 2;
                    cp16(st + (PA_L + r * LDS_ + q * 8) * 2, Ahi + APL + (long)(bm + r) * E_ + k0 + q * 8);
                } else if (idx < 1280) {
                    const int r = (idx - 1024) >> 2;
                    cp16(st + (PB_H + r * LDS_ + q * 8) * 2, Bhi + (long)(bn + r) * E_ + k0 + q * 8);
                } else {
                    const int r = (idx - 1280) >> 2;
                    cp16(st + (PB_L + r * LDS_ + q * 8) * 2, Bhi + BPL + (long)(bn + r) * E_ + k0 + q * 8);
                }
            }
        }
        CP_COMMIT();
    };

    issue(0); issue(1);
    for (int c = 0; c < 24; c++) {
        cp_wait<1>();
        __syncthreads();
        issue(c + 2);
        const uint32_t base = sbase + (uint32_t)((c % 3) * PSTG) * 2;
        #pragma unroll
        for (int ks = 0; ks < 2; ks++) {
            unsigned ah[2][4], al[2][4], bh[2][4], bl[2][4];
            #pragma unroll
            for (int mi = 0; mi < 2; mi++) {
                const uint32_t aoff =
                    ((warp_m * 32 + mi * 16 + (lane & 15)) * LDS_ + ks * 16 + ((lane >> 4) << 3)) * 2;
                ldsm4(ah[mi], base + aoff);
                ldsm4(al[mi], base + PA_L * 2 + aoff);
            }
            #pragma unroll
            for (int np = 0; np < 2; np++) {
                const uint32_t boff =
                    ((warp_n * 32 + np * 16 + ((lane >> 4) & 1) * 8 + (lane & 7)) * LDS_
                     + ks * 16 + ((lane >> 3) & 1) * 8) * 2;
                ldsm4(bh[np], base + PB_H * 2 + boff);
                ldsm4(bl[np], base + PB_L * 2 + boff);
            }
            #pragma unroll
            for (int mi = 0; mi < 2; mi++)
                #pragma unroll
                for (int ni = 0; ni < 4; ni++) {
                    const unsigned* BH = &bh[ni >> 1][(ni & 1) * 2];
                    const unsigned* BL = &bl[ni >> 1][(ni & 1) * 2];
                    mma16816(acc[mi][ni], ah[mi], BH);
                    mma16816(acc[mi][ni], ah[mi], BL);
                    mma16816(acc[mi][ni], al[mi], BH);
                }
        }
    }
}

// QKV fused over blockIdx.z (0=Q scaled, 1=K, 2=V transposed)
__global__ void __launch_bounds__(256)
proj_qkv(const __half* __restrict__ hs,
         const __half* __restrict__ w0, const __half* __restrict__ w1, const __half* __restrict__ w2,
         const float* __restrict__ b0, const float* __restrict__ b1, const float* __restrict__ b2,
         __half* __restrict__ qo, __half* __restrict__ ko, __half* __restrict__ vo)
{
    extern __shared__ char smem[];
    const uint32_t sbase = smem_u32(smem);
    const int tid = threadIdx.x, lane = tid & 31, wid = tid >> 5;
    const int warp_m = wid >> 1, warp_n = wid & 1;
    const int bm = blockIdx.y * 128, bn = blockIdx.x * 64, z = blockIdx.z;

    const __half* W    = (z == 0) ? w0 : (z == 1) ? w1 : w2;
    const float*  bias = (z == 0) ? b0 : (z == 1) ? b1 : b2;

    float acc[2][4][4] = {};
    proj_main(hs, W, MPL, WPL, bm, bn, tid, lane, warp_m, warp_n, sbase, acc);

    const float scale = (z == 0) ? SCALE_ : 1.f;
    #pragma unroll
    for (int mi = 0; mi < 2; mi++)
        #pragma unroll
        for (int ni = 0; ni < 4; ni++) {
            const int gc = bn + warp_n * 32 + ni * 8 + (lane & 3) * 2;
            const float bb0 = bias[gc], bb1 = bias[gc + 1];
            #pragma unroll
            for (int r = 0; r < 2; r++) {
                const int gm = bm + warp_m * 32 + mi * 16 + (lane >> 2) + r * 8;
                const float v0 = (acc[mi][ni][r * 2 + 0] + bb0) * scale;
                const float v1 = (acc[mi][ni][r * 2 + 1] + bb1) * scale;
                const int b = gm / S_, s = gm % S_, hh = gc >> 6, d = gc & 63;
                if (z <= 1) {
                    __half* O = (z == 0) ? qo : ko;
                    const long idx = (((long)b * H_ + hh) * S_ + s) * D_ + d;
                    *(unsigned*)(O + idx)       = ph2(v0, v1);
                    *(unsigned*)(O + MPL + idx) = pl2(v0, v1);
                } else {
                    const long idx = (((long)b * H_ + hh) * D_ + d) * S_ + s;
                    __half h0 = __float2half_rn(v0), h1 = __float2half_rn(v1);
                    vo[idx]            = h0;
                    vo[idx + S_]       = h1;
                    vo[MPL + idx]      = __float2half_rn(v0 - __half2float(h0));
                    vo[MPL + idx + S_] = __float2half_rn(v1 - __half2float(h1));
                }
            }
        }
}

// Output projection: A = ctx planes, out fp32 + bias
__global__ void __launch_bounds__(256)
proj_o(const __half* __restrict__ ctx, const __half* __restrict__ ow,
       const float* __restrict__ ob, float* __restrict__ out)
{
    extern __shared__ char smem[];
    const uint32_t sbase = smem_u32(smem);
    const int tid = threadIdx.x, lane = tid & 31, wid = tid >> 5;
    const int warp_m = wid >> 1, warp_n = wid & 1;
    const int bm = blockIdx.y * 128, bn = blockIdx.x * 64;

    float acc[2][4][4] = {};
    proj_main(ctx, ow, MPL, WPL, bm, bn, tid, lane, warp_m, warp_n, sbase, acc);

    #pragma unroll
    for (int mi = 0; mi < 2; mi++)
        #pragma unroll
        for (int ni = 0; ni < 4; ni++) {
            const int gc = bn + warp_n * 32 + ni * 8 + (lane & 3) * 2;
            const float bb0 = ob[gc], bb1 = ob[gc + 1];
            #pragma unroll
            for (int r = 0; r < 2; r++) {
                const int gm = bm + warp_m * 32 + mi * 16 + (lane >> 2) + r * 8;
                *(float2*)(out + (long)gm * E_ + gc) =
                    make_float2(acc[mi][ni][r * 2] + bb0, acc[mi][ni][r * 2 + 1] + bb1);
            }
        }
}

// ============================================================================
// Fused attention: QK^T + softmax + attn write + PV, cp.async 3-stage KV ring.
// Block = 64 query rows of one (b,h). 8 warps.
// ============================================================================
constexpr int LDSF  = 72;
constexpr int FQ_L  = 64 * LDSF;          // 4608 halfs
constexpr int FKV0  = 2 * FQ_L;           // 9216 halfs
constexpr int FSTG  = 2 * FQ_L;           // 9216 halfs per KV stage (hi+lo)
constexpr int FSMEM = (FKV0 + 3 * FSTG) * 2;   // 73728 bytes

__global__ void __launch_bounds__(256, 1)
attn_fused(const __half* __restrict__ qp, const __half* __restrict__ kp,
           const __half* __restrict__ vp, float* __restrict__ attn,
           __half* __restrict__ ctx)
{
    extern __shared__ char smem[];
    const uint32_t sbase = smem_u32(smem);
    __shared__ float s_mx[2][64], s_sm[2][64];

    const int tid = threadIdx.x, lane = tid & 31, wid = tid >> 5;
    const int warp_m = wid >> 1, warp_n = wid & 1;
    const int bm = blockIdx.x * 64;
    const int z  = blockIdx.y;

    const __half* qbase = qp + ((long)z * S_ + bm) * D_;
    const __half* kbase = kp + (long)z * S_ * D_;
    const __half* vbase = vp + (long)z * D_ * S_;
    float* attnz = attn + (long)z * S_ * S_;

    auto fillQ = [&]() {
        #pragma unroll
        for (int i = 0; i < 4; i++) {
            const int idx = tid + i * 256;
            const int pl = idx >> 9, j = idx & 511, r = j >> 3, q = j & 7;
            cp16(sbase + ((pl ? FQ_L : 0) + r * LDSF + q * 8) * 2,
                 qbase + (long)pl * MPL + (long)r * D_ + q * 8);
        }
        CP_COMMIT();
    };
    auto fillKV = [&](int slot, const __half* src, long rstride) {
        #pragma unroll
        for (int i = 0; i < 4; i++) {
            const int idx = tid + i * 256;
            const int pl = idx >> 9, j = idx & 511, r = j >> 3, q = j & 7;
            cp16(sbase + (FKV0 + slot * FSTG + pl * FQ_L + r * LDSF + q * 8) * 2,
                 src + (long)pl * MPL + (long)r * rstride + q * 8);
        }
        CP_COMMIT();
    };

    // prologue: Q + K0 + K1
    fillQ();
    fillKV(0, kbase, D_);
    fillKV(1, kbase + (long)64 * D_, D_);
    cp_wait<2>();
    __syncthreads();

    unsigned qh[4][4], ql[4][4];
    #pragma unroll
    for (int ks = 0; ks < 4; ks++) {
        const uint32_t aoff =
            ((warp_m * 16 + (lane & 15)) * LDSF + ks * 16 + ((lane >> 4) << 3)) * 2;
        ldsm4(qh[ks], sbase + aoff);
        ldsm4(ql[ks], sbase + FQ_L * 2 + aoff);
    }

    // ---- phase 1: scores ----
    float sf[9][4][4];
    #pragma unroll
    for (int c = 0; c < 9; c++)
        #pragma unroll
        for (int f = 0; f < 4; f++)
            #pragma unroll
            for (int r = 0; r < 4; r++) sf[c][f][r] = 0.f;

    #pragma unroll
    for (int c = 0; c < 9; c++) {
        cp_wait<1>();
        __syncthreads();
        if (c < 7)      fillKV((c + 2) % 3, kbase + (long)(c + 2) * 64 * D_, D_);
        else            fillKV((c + 2) % 3, vbase + (long)(c - 7) * 64, S_);
        const uint32_t baseH = sbase + (FKV0 + (c % 3) * FSTG) * 2;
        const uint32_t baseL = baseH + FQ_L * 2;
        #pragma unroll
        for (int ks = 0; ks < 4; ks++) {
            unsigned kh[2][4], kl[2][4];
            #pragma unroll
            for (int np = 0; np < 2; np++) {
                const uint32_t boff =
                    ((warp_n * 32 + np * 16 + ((lane >> 4) & 1) * 8 + (lane & 7)) * LDSF
                     + ks * 16 + ((lane >> 3) & 1) * 8) * 2;
                ldsm4(kh[np], baseH + boff);
                ldsm4(kl[np], baseL + boff);
            }
            #pragma unroll
            for (int f = 0; f < 4; f++) {
                const unsigned* BH = &kh[f >> 1][(f & 1) * 2];
                const unsigned* BL = &kl[f >> 1][(f & 1) * 2];
                mma16816(sf[c][f], qh[ks], BH);
                mma16816(sf[c][f], qh[ks], BL);
                mma16816(sf[c][f], ql[ks], BH);
            }
        }
    }

    // ---- phase 2: softmax ----
    const int r1 = warp_m * 16 + (lane >> 2), r2 = r1 + 8;
    float m1 = -INFINITY, m2 = -INFINITY;
    #pragma unroll
    for (int c = 0; c < 9; c++)
        #pragma unroll
        for (int f = 0; f < 4; f++) {
            m1 = fmaxf(m1, fmaxf(sf[c][f][0], sf[c][f][1]));
            m2 = fmaxf(m2, fmaxf(sf[c][f][2], sf[c][f][3]));
        }
    #pragma unroll
    for (int o = 1; o <= 2; o <<= 1) {
        m1 = fmaxf(m1, __shfl_xor_sync(0xffffffffu, m1, o));
        m2 = fmaxf(m2, __shfl_xor_sync(0xffffffffu, m2, o));
    }
    if ((lane & 3) == 0) { s_mx[warp_n][r1] = m1; s_mx[warp_n][r2] = m2; }
    __syncthreads();
    m1 = fmaxf(s_mx[0][r1], s_mx[1][r1]);
    m2 = fmaxf(s_mx[0][r2], s_mx[1][r2]);

    float s1 = 0.f, s2 = 0.f;
    #pragma unroll
    for (int c = 0; c < 9; c++)
        #pragma unroll
        for (int f = 0; f < 4; f++) {
            sf[c][f][0] = __expf(sf[c][f][0] - m1);
            sf[c][f][1] = __expf(sf[c][f][1] - m1);
            sf[c][f][2] = __expf(sf[c][f][2] - m2);
            sf[c][f][3] = __expf(sf[c][f][3] - m2);
            s1 += sf[c][f][0] + sf[c][f][1];
            s2 += sf[c][f][2] + sf[c][f][3];
        }
    #pragma unroll
    for (int o = 1; o <= 2; o <<= 1) {
        s1 += __shfl_xor_sync(0xffffffffu, s1, o);
        s2 += __shfl_xor_sync(0xffffffffu, s2, o);
    }
    if ((lane & 3) == 0) { s_sm[warp_n][r1] = s1; s_sm[warp_n][r2] = s2; }
    __syncthreads();
    const float inv1 = 1.f / (s_sm[0][r1] + s_sm[1][r1]);
    const float inv2 = 1.f / (s_sm[0][r2] + s_sm[1][r2]);

    // ---- phase 3: normalize + write attn ----
    #pragma unroll
    for (int c = 0; c < 9; c++)
        #pragma unroll
        for (int f = 0; f < 4; f++) {
            sf[c][f][0] *= inv1; sf[c][f][1] *= inv1;
            sf[c][f][2] *= inv2; sf[c][f][3] *= inv2;
            const int col = c * 64 + warp_n * 32 + f * 8 + (lane & 3) * 2;
            *(float2*)(attnz + (long)(bm + r1) * S_ + col) = make_float2(sf[c][f][0], sf[c][f][1]);
            *(float2*)(attnz + (long)(bm + r2) * S_ + col) = make_float2(sf[c][f][2], sf[c][f][3]);
        }

    // ---- phase 4: PV ----
    float dacc[8][4];
    #pragma unroll
    for (int f = 0; f < 8; f++)
        #pragma unroll
        for (int r = 0; r < 4; r++) dacc[f][r] = 0.f;

    #pragma unroll
    for (int c = 0; c < 9; c++) {
        cp_wait<1>();
        __syncthreads();
        if (c < 7) fillKV((c + 2) % 3, vbase + (long)(c + 2) * 64, S_);
        else       CP_COMMIT();
        const uint32_t baseH = sbase + (FKV0 + (c % 3) * FSTG) * 2;
        const uint32_t baseL = baseH + FQ_L * 2;
        #pragma unroll
        for (int g = 0; g < 2; g++) {
            unsigned ph[4], pl[4];
            {
                const float* f0 = sf[c][g * 2];
                const float* f1 = sf[c][g * 2 + 1];
                ph[0] = ph2(f0[0], f0[1]); ph[1] = ph2(f0[2], f0[3]);
                ph[2] = ph2(f1[0], f1[1]); ph[3] = ph2(f1[2], f1[3]);
                pl[0] = pl2(f0[0], f0[1]); pl[1] = pl2(f0[2], f0[3]);
                pl[2] = pl2(f1[0], f1[1]); pl[3] = pl2(f1[2], f1[3]);
            }
            const int ksv = warp_n * 2 + g;
            unsigned vh[4][4], vl[4][4];
            #pragma unroll
            for (int np = 0; np < 4; np++) {
                const uint32_t boff =
                    ((np * 16 + ((lane >> 4) & 1) * 8 + (lane & 7)) * LDSF
                     + ksv * 16 + ((lane >> 3) & 1) * 8) * 2;
                ldsm4(vh[np], baseH + boff);
                ldsm4(vl[np], baseL + boff);
            }
            #pragma unroll
            for (int f = 0; f < 8; f++) {
                const unsigned* BH = &vh[f >> 1][(f & 1) * 2];
                const unsigned* BL = &vl[f >> 1][(f & 1) * 2];
                mma16816(dacc[f], ph, BH);
                mma16816(dacc[f], ph, BL);
                mma16816(dacc[f], pl, BH);
            }
        }
    }

    // ---- phase 5: cross-warp_n reduction + ctx write ----
    __syncthreads();
    float* sred = (float*)smem;   // reuses Q area (dead)
    if (warp_n == 0) {
        #pragma unroll
        for (int f = 0; f < 8; f++)
            #pragma unroll
            for (int rr = 0; rr < 2; rr++) {
                const int row = warp_m * 16 + (lane >> 2) + rr * 8;
                const int col = f * 8 + (lane & 3) * 2;
                sred[row * 68 + col]     = dacc[f][rr * 2];
                sred[row * 68 + col + 1] = dacc[f][rr * 2 + 1];
            }
    }
    __syncthreads();
    if (warp_n == 1) {
        const int b = z / H_, h = z % H_;
        #pragma unroll
        for (int f = 0; f < 8; f++)
            #pragma unroll
            for (int rr = 0; rr < 2; rr++) {
                const int row = warp_m * 16 + (lane >> 2) + rr * 8;
                const int col = f * 8 + (lane & 3) * 2;
                const float v0 = dacc[f][rr * 2]     + sred[row * 68 + col];
                const float v1 = dacc[f][rr * 2 + 1] + sred[row * 68 + col + 1];
                const long idx = ((long)(b * S_ + bm + row)) * E_ + h * D_ + col;
                *(unsigned*)(ctx + idx)       = ph2(v0, v1);
                *(unsigned*)(ctx + MPL + idx) = pl2(v0, v1);
            }
    }
}

// ============================================================================
// Launch
// ============================================================================
extern "C" void kernel_launch(void* const* d_in, const int* in_sizes, int n_in,
                              void* d_out, int out_size)
{
    const float* hs = (const float*)d_in[0];
    const float* qw = (const float*)d_in[1];
    const float* qb = (const float*)d_in[2];
    const float* kw = (const float*)d_in[3];
    const float* kb = (const float*)d_in[4];
    const float* vw = (const float*)d_in[5];
    const float* vb = (const float*)d_in[6];
    const float* ow = (const float*)d_in[7];
    const float* ob = (const float*)d_in[8];
    float* out = (float*)d_out;

    __half *hsP, *qwP, *kwP, *vwP, *owP, *qP, *kP, *vP, *ctxP;
    float* attn_fb;
    cudaGetSymbolAddress((void**)&hsP, g_hs);
    cudaGetSymbolAddress((void**)&qwP, g_qw);
    cudaGetSymbolAddress((void**)&kwP, g_kw);
    cudaGetSymbolAddress((void**)&vwP, g_vw);
    cudaGetSymbolAddress((void**)&owP, g_ow);
    cudaGetSymbolAddress((void**)&qP,  g_q);
    cudaGetSymbolAddress((void**)&kP,  g_k);
    cudaGetSymbolAddress((void**)&vP,  g_v);
    cudaGetSymbolAddress((void**)&ctxP, g_ctx);
    cudaGetSymbolAddress((void**)&attn_fb, g_attn);
    float* attn = ((long)out_size >= OUT1 + NATTN) ? (out + OUT1) : attn_fb;

    cudaFuncSetAttribute(proj_qkv,   cudaFuncAttributeMaxDynamicSharedMemorySize, PSMEM);
    cudaFuncSetAttribute(proj_o,     cudaFuncAttributeMaxDynamicSharedMemorySize, PSMEM);
    cudaFuncSetAttribute(attn_fused, cudaFuncAttributeMaxDynamicSharedMemorySize, FSMEM);

    // 0. pack inputs to hi/lo fp16 planes
    pack_split<<<1024, 256>>>(hs, hsP, MPL);
    pack_split<<<288, 256>>>(qw, qwP, WPL);
    pack_split<<<288, 256>>>(kw, kwP, WPL);
    pack_split<<<288, 256>>>(vw, vwP, WPL);
    pack_split<<<288, 256>>>(ow, owP, WPL);

    // 1. fused QKV projections (z: 0=Q scaled, 1=K, 2=V transposed)
    dim3 gproj(E_ / 64, BS_ / 128, 3);
    proj_qkv<<<gproj, 256, PSMEM>>>(hsP, qwP, kwP, vwP, qb, kb, vb, qP, kP, vP);

    // 2. fused scores + softmax + attn write + PV
    dim3 gf(S_ / 64, B_ * H_, 1);
    attn_fused<<<gf, 256, FSMEM>>>(qP, kP, vP, attn, ctxP);

    // 3. output projection
    dim3 go(E_ / 64, BS_ / 128, 1);
    proj_o<<<go, 256, PSMEM>>>(ctxP, owP, ob, out);
}

// round 6
// speedup vs baseline: 1.3438x; 1.3438x over previous
#include <cuda_runtime.h>
#include <cuda_fp16.h>
#include <math.h>
#include <stdint.h>

// ---------------- problem constants ----------------
constexpr int B_  = 32;
constexpr int S_  = 576;
constexpr int E_  = 768;
constexpr int H_  = 12;
constexpr int D_  = 64;
constexpr int BS_ = B_ * S_;                    // 18432
constexpr long OUT1  = (long)BS_ * E_;          // 14,155,776
constexpr long NATTN = (long)B_ * H_ * S_ * S_; // 127,401,984
constexpr float SCALE_ = 0.125f;
constexpr long MPL = (long)BS_ * E_;
constexpr long WPL = (long)E_ * E_;

// ---------------- device scratch ----------------
__device__ __half g_hs [MPL];          // activations: single fp16 plane
__device__ __half g_qw [2 * WPL];      // weights: hi plane, lo plane
__device__ __half g_kw [2 * WPL];
__device__ __half g_vw [2 * WPL];
__device__ __half g_ow [2 * WPL];
__device__ __half g_q  [2 * MPL];      // [B,H,S,D] hi/lo, pre-scaled by 0.125
__device__ __half g_k  [2 * MPL];      // [B,H,S,D] hi/lo
__device__ __half g_v  [2 * MPL];      // [B,H,D,S] hi/lo (transposed)
__device__ __half g_ctx[MPL];          // [B*S, E] single plane
__device__ float  g_attn[(size_t)NATTN];

// ---------------- helpers ----------------
__device__ __forceinline__ uint32_t smem_u32(const void* p) {
    uint32_t a;
    asm("{ .reg .u64 t; cvta.to.shared.u64 t, %1; cvt.u32.u64 %0, t; }" : "=r"(a) : "l"(p));
    return a;
}
__device__ __forceinline__ void cp16(uint32_t saddr, const void* gaddr) {
    asm volatile("cp.async.cg.shared.global [%0], [%1], 16;" :: "r"(saddr), "l"(gaddr));
}
#define CP_COMMIT() asm volatile("cp.async.commit_group;" ::: "memory")
template<int N> __device__ __forceinline__ void cp_wait() {
    asm volatile("cp.async.wait_group %0;" :: "n"(N) : "memory");
}
__device__ __forceinline__ unsigned u32h2(__half a, __half b) {
    return (unsigned)__half_as_ushort(a) | ((unsigned)__half_as_ushort(b) << 16);
}
__device__ __forceinline__ unsigned ph2(float a, float b) {
    return u32h2(__float2half_rn(a), __float2half_rn(b));
}
__device__ __forceinline__ unsigned pl2(float a, float b) {
    __half ha = __float2half_rn(a), hb = __float2half_rn(b);
    return u32h2(__float2half_rn(a - __half2float(ha)),
                 __float2half_rn(b - __half2float(hb)));
}
__device__ __forceinline__ void ldsm4(unsigned* r, uint32_t addr) {
    asm volatile("ldmatrix.sync.aligned.m8n8.x4.shared.b16 {%0,%1,%2,%3}, [%4];"
                 : "=r"(r[0]), "=r"(r[1]), "=r"(r[2]), "=r"(r[3]) : "r"(addr));
}
__device__ __forceinline__ void mma16816(float* d, const unsigned* a, const unsigned* b) {
    asm volatile(
        "mma.sync.aligned.m16n8k16.row.col.f32.f16.f16.f32 "
        "{%0,%1,%2,%3}, {%4,%5,%6,%7}, {%8,%9}, {%0,%1,%2,%3};"
        : "+f"(d[0]), "+f"(d[1]), "+f"(d[2]), "+f"(d[3])
        : "r"(a[0]), "r"(a[1]), "r"(a[2]), "r"(a[3]), "r"(b[0]), "r"(b[1]));
}

// ---------------- pack kernels ----------------
__global__ void pack_one(const float* __restrict__ src, __half* __restrict__ dst, long n) {
    const long stride = (long)gridDim.x * blockDim.x * 2;
    for (long i = ((long)blockIdx.x * blockDim.x + threadIdx.x) * 2; i < n; i += stride) {
        float2 f = *(const float2*)(src + i);
        *(unsigned*)(dst + i) = ph2(f.x, f.y);
    }
}
__global__ void pack_two(const float* __restrict__ src, __half* __restrict__ dhi, long n) {
    __half* dlo = dhi + n;
    const long stride = (long)gridDim.x * blockDim.x * 2;
    for (long i = ((long)blockIdx.x * blockDim.x + threadIdx.x) * 2; i < n; i += stride) {
        float2 f = *(const float2*)(src + i);
        *(unsigned*)(dhi + i) = ph2(f.x, f.y);
        *(unsigned*)(dlo + i) = pl2(f.x, f.y);
    }
}

// ============================================================================
// Projection GEMM core: 128x64 block, 8 warps (32x32), BK=32, fp16 2-pass
// (A plain fp16; B hi+lo). 3-stage cp.async ring. K=768 (24 chunks).
// ============================================================================
constexpr int LDS_  = 40;                // halfs per smem row
constexpr int PBH   = 128 * LDS_;        // 5120
constexpr int PBL   = PBH + 64 * LDS_;   // 7680
constexpr int PSTG  = PBL + 64 * LDS_;   // 10240 halfs per stage
constexpr int PSMEM = 3 * PSTG * 2;      // 61440 bytes

__device__ __forceinline__ void proj_main(
    const __half* __restrict__ A, const __half* __restrict__ Bhi,
    int bm, int bn, int tid, int lane,
    int warp_m, int warp_n, uint32_t sbase, float acc[2][4][4])
{
    auto issue = [&](int c) {
        if (c < 24) {
            const uint32_t st = sbase + (uint32_t)((c % 3) * PSTG) * 2;
            const int k0 = c * 32;
            #pragma unroll
            for (int i = 0; i < 4; i++) {
                const int idx = tid + i * 256;
                const int q = idx & 3;
                if (idx < 512) {
                    const int r = idx >> 2;
                    cp16(st + (r * LDS_ + q * 8) * 2, A + (long)(bm + r) * E_ + k0 + q * 8);
                } else if (idx < 768) {
                    const int r = (idx - 512) >> 2;
                    cp16(st + (PBH + r * LDS_ + q * 8) * 2, Bhi + (long)(bn + r) * E_ + k0 + q * 8);
                } else {
                    const int r = (idx - 768) >> 2;
                    cp16(st + (PBL + r * LDS_ + q * 8) * 2, Bhi + WPL + (long)(bn + r) * E_ + k0 + q * 8);
                }
            }
        }
        CP_COMMIT();
    };

    issue(0); issue(1);
    for (int c = 0; c < 24; c++) {
        cp_wait<1>();
        __syncthreads();
        issue(c + 2);
        const uint32_t base = sbase + (uint32_t)((c % 3) * PSTG) * 2;
        #pragma unroll
        for (int ks = 0; ks < 2; ks++) {
            unsigned ah[2][4], bh[2][4], bl[2][4];
            #pragma unroll
            for (int mi = 0; mi < 2; mi++) {
                const uint32_t aoff =
                    ((warp_m * 32 + mi * 16 + (lane & 15)) * LDS_ + ks * 16 + ((lane >> 4) << 3)) * 2;
                ldsm4(ah[mi], base + aoff);
            }
            #pragma unroll
            for (int np = 0; np < 2; np++) {
                const uint32_t boff =
                    ((warp_n * 32 + np * 16 + ((lane >> 4) & 1) * 8 + (lane & 7)) * LDS_
                     + ks * 16 + ((lane >> 3) & 1) * 8) * 2;
                ldsm4(bh[np], base + PBH * 2 + boff);
                ldsm4(bl[np], base + PBL * 2 + boff);
            }
            #pragma unroll
            for (int mi = 0; mi < 2; mi++)
                #pragma unroll
                for (int ni = 0; ni < 4; ni++) {
                    mma16816(acc[mi][ni], ah[mi], &bh[ni >> 1][(ni & 1) * 2]);
                    mma16816(acc[mi][ni], ah[mi], &bl[ni >> 1][(ni & 1) * 2]);
                }
        }
    }
}

// QKV fused over blockIdx.z (0=Q scaled, 1=K, 2=V transposed)
__global__ void __launch_bounds__(256, 2)
proj_qkv(const __half* __restrict__ hs,
         const __half* __restrict__ w0, const __half* __restrict__ w1, const __half* __restrict__ w2,
         const float* __restrict__ b0, const float* __restrict__ b1, const float* __restrict__ b2,
         __half* __restrict__ qo, __half* __restrict__ ko, __half* __restrict__ vo)
{
    extern __shared__ char smem[];
    const uint32_t sbase = smem_u32(smem);
    const int tid = threadIdx.x, lane = tid & 31, wid = tid >> 5;
    const int warp_m = wid >> 1, warp_n = wid & 1;
    const int bm = blockIdx.y * 128, bn = blockIdx.x * 64, z = blockIdx.z;

    const __half* W    = (z == 0) ? w0 : (z == 1) ? w1 : w2;
    const float*  bias = (z == 0) ? b0 : (z == 1) ? b1 : b2;

    float acc[2][4][4] = {};
    proj_main(hs, W, bm, bn, tid, lane, warp_m, warp_n, sbase, acc);

    const float scale = (z == 0) ? SCALE_ : 1.f;
    #pragma unroll
    for (int mi = 0; mi < 2; mi++)
        #pragma unroll
        for (int ni = 0; ni < 4; ni++) {
            const int gc = bn + warp_n * 32 + ni * 8 + (lane & 3) * 2;
            const float bb0 = bias[gc], bb1 = bias[gc + 1];
            #pragma unroll
            for (int r = 0; r < 2; r++) {
                const int gm = bm + warp_m * 32 + mi * 16 + (lane >> 2) + r * 8;
                const float v0 = (acc[mi][ni][r * 2 + 0] + bb0) * scale;
                const float v1 = (acc[mi][ni][r * 2 + 1] + bb1) * scale;
                const int b = gm / S_, s = gm % S_, hh = gc >> 6, d = gc & 63;
                if (z <= 1) {
                    __half* O = (z == 0) ? qo : ko;
                    const long idx = (((long)b * H_ + hh) * S_ + s) * D_ + d;
                    *(unsigned*)(O + idx)       = ph2(v0, v1);
                    *(unsigned*)(O + MPL + idx) = pl2(v0, v1);
                } else {
                    const long idx = (((long)b * H_ + hh) * D_ + d) * S_ + s;
                    __half h0 = __float2half_rn(v0), h1 = __float2half_rn(v1);
                    vo[idx]            = h0;
                    vo[idx + S_]       = h1;
                    vo[MPL + idx]      = __float2half_rn(v0 - __half2float(h0));
                    vo[MPL + idx + S_] = __float2half_rn(v1 - __half2float(h1));
                }
            }
        }
}

// Output projection: ctx (single plane fp16) x ow (hi/lo), fp32 out + bias
__global__ void __launch_bounds__(256, 2)
proj_o(const __half* __restrict__ ctx, const __half* __restrict__ ow,
       const float* __restrict__ ob, float* __restrict__ out)
{
    extern __shared__ char smem[];
    const uint32_t sbase = smem_u32(smem);
    const int tid = threadIdx.x, lane = tid & 31, wid = tid >> 5;
    const int warp_m = wid >> 1, warp_n = wid & 1;
    const int bm = blockIdx.y * 128, bn = blockIdx.x * 64;

    float acc[2][4][4] = {};
    proj_main(ctx, ow, bm, bn, tid, lane, warp_m, warp_n, sbase, acc);

    #pragma unroll
    for (int mi = 0; mi < 2; mi++)
        #pragma unroll
        for (int ni = 0; ni < 4; ni++) {
            const int gc = bn + warp_n * 32 + ni * 8 + (lane & 3) * 2;
            const float bb0 = ob[gc], bb1 = ob[gc + 1];
            #pragma unroll
            for (int r = 0; r < 2; r++) {
                const int gm = bm + warp_m * 32 + mi * 16 + (lane >> 2) + r * 8;
                *(float2*)(out + (long)gm * E_ + gc) =
                    make_float2(acc[mi][ni][r * 2] + bb0, acc[mi][ni][r * 2 + 1] + bb1);
            }
        }
}

// ============================================================================
// Fused attention: QK^T (3-pass) + softmax + attn write + PV (2-pass).
// Block = 64 query rows of one (b,h). 8 warps. cp.async 3-stage KV ring.
// ============================================================================
constexpr int LDSF  = 72;
constexpr int FQ_L  = 64 * LDSF;               // 4608 halfs per plane
constexpr int FKV0  = 2 * FQ_L;
constexpr int FSTG  = 2 * FQ_L;                // hi+lo per stage
constexpr int FSMEM = (FKV0 + 3 * FSTG) * 2;   // 73728 bytes

__global__ void __launch_bounds__(256, 1)
attn_fused(const __half* __restrict__ qp, const __half* __restrict__ kp,
           const __half* __restrict__ vp, float* __restrict__ attn,
           __half* __restrict__ ctx)
{
    extern __shared__ char smem[];
    const uint32_t sbase = smem_u32(smem);
    __shared__ float s_mx[2][64], s_sm[2][64];

    const int tid = threadIdx.x, lane = tid & 31, wid = tid >> 5;
    const int warp_m = wid >> 1, warp_n = wid & 1;
    const int bm = blockIdx.x * 64;
    const int z  = blockIdx.y;

    const __half* qbase = qp + ((long)z * S_ + bm) * D_;
    const __half* kbase = kp + (long)z * S_ * D_;
    const __half* vbase = vp + (long)z * D_ * S_;
    float* attnz = attn + (long)z * S_ * S_;

    auto fillQ = [&]() {
        #pragma unroll
        for (int i = 0; i < 4; i++) {
            const int idx = tid + i * 256;
            const int pl = idx >> 9, j = idx & 511, r = j >> 3, q = j & 7;
            cp16(sbase + ((pl ? FQ_L : 0) + r * LDSF + q * 8) * 2,
                 qbase + (long)pl * MPL + (long)r * D_ + q * 8);
        }
        CP_COMMIT();
    };
    auto fillKV = [&](int slot, const __half* src, long rstride) {
        #pragma unroll
        for (int i = 0; i < 4; i++) {
            const int idx = tid + i * 256;
            const int pl = idx >> 9, j = idx & 511, r = j >> 3, q = j & 7;
            cp16(sbase + (FKV0 + slot * FSTG + pl * FQ_L + r * LDSF + q * 8) * 2,
                 src + (long)pl * MPL + (long)r * rstride + q * 8);
        }
        CP_COMMIT();
    };

    fillQ();
    fillKV(0, kbase, D_);
    fillKV(1, kbase + (long)64 * D_, D_);
    cp_wait<2>();
    __syncthreads();

    unsigned qh[4][4], ql[4][4];
    #pragma unroll
    for (int ks = 0; ks < 4; ks++) {
        const uint32_t aoff =
            ((warp_m * 16 + (lane & 15)) * LDSF + ks * 16 + ((lane >> 4) << 3)) * 2;
        ldsm4(qh[ks], sbase + aoff);
        ldsm4(ql[ks], sbase + FQ_L * 2 + aoff);
    }

    // ---- phase 1: scores (3-pass) ----
    float sf[9][4][4];
    #pragma unroll
    for (int c = 0; c < 9; c++)
        #pragma unroll
        for (int f = 0; f < 4; f++)
            #pragma unroll
            for (int r = 0; r < 4; r++) sf[c][f][r] = 0.f;

    #pragma unroll
    for (int c = 0; c < 9; c++) {
        cp_wait<1>();
        __syncthreads();
        if (c < 7)      fillKV((c + 2) % 3, kbase + (long)(c + 2) * 64 * D_, D_);
        else            fillKV((c + 2) % 3, vbase + (long)(c - 7) * 64, S_);
        const uint32_t baseH = sbase + (FKV0 + (c % 3) * FSTG) * 2;
        const uint32_t baseL = baseH + FQ_L * 2;
        #pragma unroll
        for (int ks = 0; ks < 4; ks++) {
            unsigned kh[2][4], kl[2][4];
            #pragma unroll
            for (int np = 0; np < 2; np++) {
                const uint32_t boff =
                    ((warp_n * 32 + np * 16 + ((lane >> 4) & 1) * 8 + (lane & 7)) * LDSF
                     + ks * 16 + ((lane >> 3) & 1) * 8) * 2;
                ldsm4(kh[np], baseH + boff);
                ldsm4(kl[np], baseL + boff);
            }
            #pragma unroll
            for (int f = 0; f < 4; f++) {
                const unsigned* BH = &kh[f >> 1][(f & 1) * 2];
                const unsigned* BL = &kl[f >> 1][(f & 1) * 2];
                mma16816(sf[c][f], qh[ks], BH);
                mma16816(sf[c][f], qh[ks], BL);
                mma16816(sf[c][f], ql[ks], BH);
            }
        }
    }

    // ---- phase 2: softmax ----
    const int r1 = warp_m * 16 + (lane >> 2), r2 = r1 + 8;
    float m1 = -INFINITY, m2 = -INFINITY;
    #pragma unroll
    for (int c = 0; c < 9; c++)
        #pragma unroll
        for (int f = 0; f < 4; f++) {
            m1 = fmaxf(m1, fmaxf(sf[c][f][0], sf[c][f][1]));
            m2 = fmaxf(m2, fmaxf(sf[c][f][2], sf[c][f][3]));
        }
    #pragma unroll
    for (int o = 1; o <= 2; o <<= 1) {
        m1 = fmaxf(m1, __shfl_xor_sync(0xffffffffu, m1, o));
        m2 = fmaxf(m2, __shfl_xor_sync(0xffffffffu, m2, o));
    }
    if ((lane & 3) == 0) { s_mx[warp_n][r1] = m1; s_mx[warp_n][r2] = m2; }
    __syncthreads();
    m1 = fmaxf(s_mx[0][r1], s_mx[1][r1]);
    m2 = fmaxf(s_mx[0][r2], s_mx[1][r2]);

    float s1 = 0.f, s2 = 0.f;
    #pragma unroll
    for (int c = 0; c < 9; c++)
        #pragma unroll
        for (int f = 0; f < 4; f++) {
            sf[c][f][0] = __expf(sf[c][f][0] - m1);
            sf[c][f][1] = __expf(sf[c][f][1] - m1);
            sf[c][f][2] = __expf(sf[c][f][2] - m2);
            sf[c][f][3] = __expf(sf[c][f][3] - m2);
            s1 += sf[c][f][0] + sf[c][f][1];
            s2 += sf[c][f][2] + sf[c][f][3];
        }
    #pragma unroll
    for (int o = 1; o <= 2; o <<= 1) {
        s1 += __shfl_xor_sync(0xffffffffu, s1, o);
        s2 += __shfl_xor_sync(0xffffffffu, s2, o);
    }
    if ((lane & 3) == 0) { s_sm[warp_n][r1] = s1; s_sm[warp_n][r2] = s2; }
    __syncthreads();
    const float inv1 = 1.f / (s_sm[0][r1] + s_sm[1][r1]);
    const float inv2 = 1.f / (s_sm[0][r2] + s_sm[1][r2]);

    // ---- phase 3: normalize + write attn ----
    #pragma unroll
    for (int c = 0; c < 9; c++)
        #pragma unroll
        for (int f = 0; f < 4; f++) {
            sf[c][f][0] *= inv1; sf[c][f][1] *= inv1;
            sf[c][f][2] *= inv2; sf[c][f][3] *= inv2;
            const int col = c * 64 + warp_n * 32 + f * 8 + (lane & 3) * 2;
            *(float2*)(attnz + (long)(bm + r1) * S_ + col) = make_float2(sf[c][f][0], sf[c][f][1]);
            *(float2*)(attnz + (long)(bm + r2) * S_ + col) = make_float2(sf[c][f][2], sf[c][f][3]);
        }

    // ---- phase 4: PV (2-pass: Ph*Vh + Ph*Vl) ----
    float dacc[8][4];
    #pragma unroll
    for (int f = 0; f < 8; f++)
        #pragma unroll
        for (int r = 0; r < 4; r++) dacc[f][r] = 0.f;

    #pragma unroll
    for (int c = 0; c < 9; c++) {
        cp_wait<1>();
        __syncthreads();
        if (c < 7) fillKV((c + 2) % 3, vbase + (long)(c + 2) * 64, S_);
        else       CP_COMMIT();
        const uint32_t baseH = sbase + (FKV0 + (c % 3) * FSTG) * 2;
        const uint32_t baseL = baseH + FQ_L * 2;
        #pragma unroll
        for (int g = 0; g < 2; g++) {
            unsigned ph[4];
            {
                const float* f0 = sf[c][g * 2];
                const float* f1 = sf[c][g * 2 + 1];
                ph[0] = ph2(f0[0], f0[1]); ph[1] = ph2(f0[2], f0[3]);
                ph[2] = ph2(f1[0], f1[1]); ph[3] = ph2(f1[2], f1[3]);
            }
            const int ksv = warp_n * 2 + g;
            unsigned vh[4][4], vl[4][4];
            #pragma unroll
            for (int np = 0; np < 4; np++) {
                const uint32_t boff =
                    ((np * 16 + ((lane >> 4) & 1) * 8 + (lane & 7)) * LDSF
                     + ksv * 16 + ((lane >> 3) & 1) * 8) * 2;
                ldsm4(vh[np], baseH + boff);
                ldsm4(vl[np], baseL + boff);
            }
            #pragma unroll
            for (int f = 0; f < 8; f++) {
                mma16816(dacc[f], ph, &vh[f >> 1][(f & 1) * 2]);
                mma16816(dacc[f], ph, &vl[f >> 1][(f & 1) * 2]);
            }
        }
    }

    // ---- phase 5: cross-warp_n reduction + ctx write ----
    __syncthreads();
    float* sred = (float*)smem;
    if (warp_n == 0) {
        #pragma unroll
        for (int f = 0; f < 8; f++)
            #pragma unroll
            for (int rr = 0; rr < 2; rr++) {
                const int row = warp_m * 16 + (lane >> 2) + rr * 8;
                const int col = f * 8 + (lane & 3) * 2;
                sred[row * 68 + col]     = dacc[f][rr * 2];
                sred[row * 68 + col + 1] = dacc[f][rr * 2 + 1];
            }
    }
    __syncthreads();
    if (warp_n == 1) {
        const int b = z / H_, h = z % H_;
        #pragma unroll
        for (int f = 0; f < 8; f++)
            #pragma unroll
            for (int rr = 0; rr < 2; rr++) {
                const int row = warp_m * 16 + (lane >> 2) + rr * 8;
                const int col = f * 8 + (lane & 3) * 2;
                const float v0 = dacc[f][rr * 2]     + sred[row * 68 + col];
                const float v1 = dacc[f][rr * 2 + 1] + sred[row * 68 + col + 1];
                *(unsigned*)(ctx + ((long)(b * S_ + bm + row)) * E_ + h * D_ + col) = ph2(v0, v1);
            }
    }
}

// ============================================================================
// Launch
// ============================================================================
extern "C" void kernel_launch(void* const* d_in, const int* in_sizes, int n_in,
                              void* d_out, int out_size)
{
    const float* hs = (const float*)d_in[0];
    const float* qw = (const float*)d_in[1];
    const float* qb = (const float*)d_in[2];
    const float* kw = (const float*)d_in[3];
    const float* kb = (const float*)d_in[4];
    const float* vw = (const float*)d_in[5];
    const float* vb = (const float*)d_in[6];
    const float* ow = (const float*)d_in[7];
    const float* ob = (const float*)d_in[8];
    float* out = (float*)d_out;

    __half *hsP, *qwP, *kwP, *vwP, *owP, *qP, *kP, *vP, *ctxP;
    float* attn_fb;
    cudaGetSymbolAddress((void**)&hsP, g_hs);
    cudaGetSymbolAddress((void**)&qwP, g_qw);
    cudaGetSymbolAddress((void**)&kwP, g_kw);
    cudaGetSymbolAddress((void**)&vwP, g_vw);
    cudaGetSymbolAddress((void**)&owP, g_ow);
    cudaGetSymbolAddress((void**)&qP,  g_q);
    cudaGetSymbolAddress((void**)&kP,  g_k);
    cudaGetSymbolAddress((void**)&vP,  g_v);
    cudaGetSymbolAddress((void**)&ctxP, g_ctx);
    cudaGetSymbolAddress((void**)&attn_fb, g_attn);
    float* attn = ((long)out_size >= OUT1 + NATTN) ? (out + OUT1) : attn_fb;

    cudaFuncSetAttribute(proj_qkv,   cudaFuncAttributeMaxDynamicSharedMemorySize, PSMEM);
    cudaFuncSetAttribute(proj_o,     cudaFuncAttributeMaxDynamicSharedMemorySize, PSMEM);
    cudaFuncSetAttribute(attn_fused, cudaFuncAttributeMaxDynamicSharedMemorySize, FSMEM);

    // 0. pack inputs
    pack_one<<<1024, 256>>>(hs, hsP, MPL);
    pack_two<<<288, 256>>>(qw, qwP, WPL);
    pack_two<<<288, 256>>>(kw, kwP, WPL);
    pack_two<<<288, 256>>>(vw, vwP, WPL);
    pack_two<<<288, 256>>>(ow, owP, WPL);

    // 1. fused QKV projections (2-pass)
    dim3 gproj(E_ / 64, BS_ / 128, 3);
    proj_qkv<<<gproj, 256, PSMEM>>>(hsP, qwP, kwP, vwP, qb, kb, vb, qP, kP, vP);

    // 2. fused scores + softmax + attn write + PV
    dim3 gf(S_ / 64, B_ * H_, 1);
    attn_fused<<<gf, 256, FSMEM>>>(qP, kP, vP, attn, ctxP);

    // 3. output projection (2-pass)
    dim3 go(E_ / 64, BS_ / 128, 1);
    proj_o<<<go, 256, PSMEM>>>(ctxP, owP, ob, out);
}

// round 7
// speedup vs baseline: 1.4312x; 1.0651x over previous
#include <cuda_runtime.h>
#include <cuda_fp16.h>
#include <math.h>
#include <stdint.h>

// ---------------- problem constants ----------------
constexpr int B_  = 32;
constexpr int S_  = 576;
constexpr int E_  = 768;
constexpr int H_  = 12;
constexpr int D_  = 64;
constexpr int BS_ = B_ * S_;                    // 18432
constexpr long OUT1  = (long)BS_ * E_;          // 14,155,776
constexpr long NATTN = (long)B_ * H_ * S_ * S_; // 127,401,984
constexpr float SCALE_ = 0.125f;
constexpr long MPL = (long)BS_ * E_;
constexpr long WPL = (long)E_ * E_;

// ---------------- device scratch ----------------
__device__ __half g_hs [MPL];          // activations: single fp16 plane
__device__ __half g_qw [2 * WPL];      // weights: hi plane, lo plane
__device__ __half g_kw [2 * WPL];
__device__ __half g_vw [2 * WPL];
__device__ __half g_ow [2 * WPL];
__device__ __half g_q  [2 * MPL];      // [B,H,S,D] hi/lo, pre-scaled by 0.125
__device__ __half g_k  [2 * MPL];      // [B,H,S,D] hi/lo
__device__ __half g_v  [2 * MPL];      // [B,H,D,S] hi/lo (transposed)
__device__ __half g_ctx[MPL];          // [B*S, E] single plane
__device__ float  g_attn[(size_t)NATTN];

// ---------------- helpers ----------------
__device__ __forceinline__ uint32_t smem_u32(const void* p) {
    uint32_t a;
    asm("{ .reg .u64 t; cvta.to.shared.u64 t, %1; cvt.u32.u64 %0, t; }" : "=r"(a) : "l"(p));
    return a;
}
__device__ __forceinline__ void cp16(uint32_t saddr, const void* gaddr) {
    asm volatile("cp.async.cg.shared.global [%0], [%1], 16;" :: "r"(saddr), "l"(gaddr));
}
#define CP_COMMIT() asm volatile("cp.async.commit_group;" ::: "memory")
template<int N> __device__ __forceinline__ void cp_wait() {
    asm volatile("cp.async.wait_group %0;" :: "n"(N) : "memory");
}
__device__ __forceinline__ unsigned u32h2(__half a, __half b) {
    return (unsigned)__half_as_ushort(a) | ((unsigned)__half_as_ushort(b) << 16);
}
__device__ __forceinline__ unsigned ph2(float a, float b) {
    return u32h2(__float2half_rn(a), __float2half_rn(b));
}
__device__ __forceinline__ unsigned pl2(float a, float b) {
    __half ha = __float2half_rn(a), hb = __float2half_rn(b);
    return u32h2(__float2half_rn(a - __half2float(ha)),
                 __float2half_rn(b - __half2float(hb)));
}
__device__ __forceinline__ void ldsm4(unsigned* r, uint32_t addr) {
    asm volatile("ldmatrix.sync.aligned.m8n8.x4.shared.b16 {%0,%1,%2,%3}, [%4];"
                 : "=r"(r[0]), "=r"(r[1]), "=r"(r[2]), "=r"(r[3]) : "r"(addr));
}
__device__ __forceinline__ void mma16816(float* d, const unsigned* a, const unsigned* b) {
    asm volatile(
        "mma.sync.aligned.m16n8k16.row.col.f32.f16.f16.f32 "
        "{%0,%1,%2,%3}, {%4,%5,%6,%7}, {%8,%9}, {%0,%1,%2,%3};"
        : "+f"(d[0]), "+f"(d[1]), "+f"(d[2]), "+f"(d[3])
        : "r"(a[0]), "r"(a[1]), "r"(a[2]), "r"(a[3]), "r"(b[0]), "r"(b[1]));
}

// ---------------- pack kernels ----------------
__global__ void pack_one(const float* __restrict__ src, __half* __restrict__ dst, long n) {
    const long stride = (long)gridDim.x * blockDim.x * 2;
    for (long i = ((long)blockIdx.x * blockDim.x + threadIdx.x) * 2; i < n; i += stride) {
        float2 f = *(const float2*)(src + i);
        *(unsigned*)(dst + i) = ph2(f.x, f.y);
    }
}
__global__ void pack_two(const float* __restrict__ src, __half* __restrict__ dhi, long n) {
    __half* dlo = dhi + n;
    const long stride = (long)gridDim.x * blockDim.x * 2;
    for (long i = ((long)blockIdx.x * blockDim.x + threadIdx.x) * 2; i < n; i += stride) {
        float2 f = *(const float2*)(src + i);
        *(unsigned*)(dhi + i) = ph2(f.x, f.y);
        *(unsigned*)(dlo + i) = pl2(f.x, f.y);
    }
}

// ============================================================================
// Projection GEMM core: 128x128 block, 8 warps (64x32 warp tile:
// warp_m=wid>>2 in {0,1}, warp_n=wid&3 in {0..3}), BK=32, fp16 2-pass
// (A plain fp16; B hi+lo). 3-stage cp.async ring, 2 CTAs/SM. K=768 (24 chunks).
// ============================================================================
constexpr int LDS_  = 40;                 // halfs per smem row
constexpr int PBH   = 128 * LDS_;         // 5120  (A tile 128x32)
constexpr int PBL   = PBH + 128 * LDS_;   // 10240 (Bh tile 128x32)
constexpr int PSTG  = PBL + 128 * LDS_;   // 15360 halfs per stage
constexpr int PSMEM = 3 * PSTG * 2;       // 92160 bytes

__device__ __forceinline__ void proj_main(
    const __half* __restrict__ A, const __half* __restrict__ Bhi,
    int bm, int bn, int tid, int lane,
    int warp_m, int warp_n, uint32_t sbase, float acc[4][4][4])
{
    auto issue = [&](int c) {
        if (c < 24) {
            const uint32_t st = sbase + (uint32_t)((c % 3) * PSTG) * 2;
            const int k0 = c * 32;
            #pragma unroll
            for (int i = 0; i < 6; i++) {
                const int idx = tid + i * 256;
                const int q = idx & 3;
                if (idx < 512) {
                    const int r = idx >> 2;
                    cp16(st + (r * LDS_ + q * 8) * 2, A + (long)(bm + r) * E_ + k0 + q * 8);
                } else if (idx < 1024) {
                    const int r = (idx - 512) >> 2;
                    cp16(st + (PBH + r * LDS_ + q * 8) * 2, Bhi + (long)(bn + r) * E_ + k0 + q * 8);
                } else {
                    const int r = (idx - 1024) >> 2;
                    cp16(st + (PBL + r * LDS_ + q * 8) * 2, Bhi + WPL + (long)(bn + r) * E_ + k0 + q * 8);
                }
            }
        }
        CP_COMMIT();
    };

    issue(0); issue(1);
    for (int c = 0; c < 24; c++) {
        cp_wait<1>();
        __syncthreads();
        issue(c + 2);
        const uint32_t base = sbase + (uint32_t)((c % 3) * PSTG) * 2;
        #pragma unroll
        for (int ks = 0; ks < 2; ks++) {
            unsigned ah[4][4], bh[2][4], bl[2][4];
            #pragma unroll
            for (int mi = 0; mi < 4; mi++) {
                const uint32_t aoff =
                    ((warp_m * 64 + mi * 16 + (lane & 15)) * LDS_ + ks * 16 + ((lane >> 4) << 3)) * 2;
                ldsm4(ah[mi], base + aoff);
            }
            #pragma unroll
            for (int np = 0; np < 2; np++) {
                const uint32_t boff =
                    ((warp_n * 32 + np * 16 + ((lane >> 4) & 1) * 8 + (lane & 7)) * LDS_
                     + ks * 16 + ((lane >> 3) & 1) * 8) * 2;
                ldsm4(bh[np], base + PBH * 2 + boff);
                ldsm4(bl[np], base + PBL * 2 + boff);
            }
            #pragma unroll
            for (int mi = 0; mi < 4; mi++)
                #pragma unroll
                for (int ni = 0; ni < 4; ni++) {
                    mma16816(acc[mi][ni], ah[mi], &bh[ni >> 1][(ni & 1) * 2]);
                    mma16816(acc[mi][ni], ah[mi], &bl[ni >> 1][(ni & 1) * 2]);
                }
        }
    }
}

// QKV fused over blockIdx.z (0=Q scaled, 1=K, 2=V transposed)
__global__ void __launch_bounds__(256, 2)
proj_qkv(const __half* __restrict__ hs,
         const __half* __restrict__ w0, const __half* __restrict__ w1, const __half* __restrict__ w2,
         const float* __restrict__ b0, const float* __restrict__ b1, const float* __restrict__ b2,
         __half* __restrict__ qo, __half* __restrict__ ko, __half* __restrict__ vo)
{
    extern __shared__ char smem[];
    const uint32_t sbase = smem_u32(smem);
    const int tid = threadIdx.x, lane = tid & 31, wid = tid >> 5;
    const int warp_m = wid >> 2, warp_n = wid & 3;
    const int bm = blockIdx.y * 128, bn = blockIdx.x * 128, z = blockIdx.z;

    const __half* W    = (z == 0) ? w0 : (z == 1) ? w1 : w2;
    const float*  bias = (z == 0) ? b0 : (z == 1) ? b1 : b2;

    float acc[4][4][4] = {};
    proj_main(hs, W, bm, bn, tid, lane, warp_m, warp_n, sbase, acc);

    const float scale = (z == 0) ? SCALE_ : 1.f;
    #pragma unroll
    for (int mi = 0; mi < 4; mi++)
        #pragma unroll
        for (int ni = 0; ni < 4; ni++) {
            const int gc = bn + warp_n * 32 + ni * 8 + (lane & 3) * 2;
            const float bb0 = bias[gc], bb1 = bias[gc + 1];
            #pragma unroll
            for (int r = 0; r < 2; r++) {
                const int gm = bm + warp_m * 64 + mi * 16 + (lane >> 2) + r * 8;
                const float v0 = (acc[mi][ni][r * 2 + 0] + bb0) * scale;
                const float v1 = (acc[mi][ni][r * 2 + 1] + bb1) * scale;
                const int b = gm / S_, s = gm % S_, hh = gc >> 6, d = gc & 63;
                if (z <= 1) {
                    __half* O = (z == 0) ? qo : ko;
                    const long idx = (((long)b * H_ + hh) * S_ + s) * D_ + d;
                    *(unsigned*)(O + idx)       = ph2(v0, v1);
                    *(unsigned*)(O + MPL + idx) = pl2(v0, v1);
                } else {
                    const long idx = (((long)b * H_ + hh) * D_ + d) * S_ + s;
                    __half h0 = __float2half_rn(v0), h1 = __float2half_rn(v1);
                    vo[idx]            = h0;
                    vo[idx + S_]       = h1;
                    vo[MPL + idx]      = __float2half_rn(v0 - __half2float(h0));
                    vo[MPL + idx + S_] = __float2half_rn(v1 - __half2float(h1));
                }
            }
        }
}

// Output projection: ctx (single plane fp16) x ow (hi/lo), fp32 out + bias
__global__ void __launch_bounds__(256, 2)
proj_o(const __half* __restrict__ ctx, const __half* __restrict__ ow,
       const float* __restrict__ ob, float* __restrict__ out)
{
    extern __shared__ char smem[];
    const uint32_t sbase = smem_u32(smem);
    const int tid = threadIdx.x, lane = tid & 31, wid = tid >> 5;
    const int warp_m = wid >> 2, warp_n = wid & 3;
    const int bm = blockIdx.y * 128, bn = blockIdx.x * 128;

    float acc[4][4][4] = {};
    proj_main(ctx, ow, bm, bn, tid, lane, warp_m, warp_n, sbase, acc);

    #pragma unroll
    for (int mi = 0; mi < 4; mi++)
        #pragma unroll
        for (int ni = 0; ni < 4; ni++) {
            const int gc = bn + warp_n * 32 + ni * 8 + (lane & 3) * 2;
            const float bb0 = ob[gc], bb1 = ob[gc + 1];
            #pragma unroll
            for (int r = 0; r < 2; r++) {
                const int gm = bm + warp_m * 64 + mi * 16 + (lane >> 2) + r * 8;
                *(float2*)(out + (long)gm * E_ + gc) =
                    make_float2(acc[mi][ni][r * 2] + bb0, acc[mi][ni][r * 2 + 1] + bb1);
            }
        }
}

// ============================================================================
// Fused attention: QK^T (3-pass) + softmax + attn write + PV (2-pass).
// Block = 64 query rows of one (b,h). 8 warps. cp.async 3-stage KV ring.
// (unchanged from R6)
// ============================================================================
constexpr int LDSF  = 72;
constexpr int FQ_L  = 64 * LDSF;               // 4608 halfs per plane
constexpr int FKV0  = 2 * FQ_L;
constexpr int FSTG  = 2 * FQ_L;                // hi+lo per stage
constexpr int FSMEM = (FKV0 + 3 * FSTG) * 2;   // 73728 bytes

__global__ void __launch_bounds__(256, 1)
attn_fused(const __half* __restrict__ qp, const __half* __restrict__ kp,
           const __half* __restrict__ vp, float* __restrict__ attn,
           __half* __restrict__ ctx)
{
    extern __shared__ char smem[];
    const uint32_t sbase = smem_u32(smem);
    __shared__ float s_mx[2][64], s_sm[2][64];

    const int tid = threadIdx.x, lane = tid & 31, wid = tid >> 5;
    const int warp_m = wid >> 1, warp_n = wid & 1;
    const int bm = blockIdx.x * 64;
    const int z  = blockIdx.y;

    const __half* qbase = qp + ((long)z * S_ + bm) * D_;
    const __half* kbase = kp + (long)z * S_ * D_;
    const __half* vbase = vp + (long)z * D_ * S_;
    float* attnz = attn + (long)z * S_ * S_;

    auto fillQ = [&]() {
        #pragma unroll
        for (int i = 0; i < 4; i++) {
            const int idx = tid + i * 256;
            const int pl = idx >> 9, j = idx & 511, r = j >> 3, q = j & 7;
            cp16(sbase + ((pl ? FQ_L : 0) + r * LDSF + q * 8) * 2,
                 qbase + (long)pl * MPL + (long)r * D_ + q * 8);
        }
        CP_COMMIT();
    };
    auto fillKV = [&](int slot, const __half* src, long rstride) {
        #pragma unroll
        for (int i = 0; i < 4; i++) {
            const int idx = tid + i * 256;
            const int pl = idx >> 9, j = idx & 511, r = j >> 3, q = j & 7;
            cp16(sbase + (FKV0 + slot * FSTG + pl * FQ_L + r * LDSF + q * 8) * 2,
                 src + (long)pl * MPL + (long)r * rstride + q * 8);
        }
        CP_COMMIT();
    };

    fillQ();
    fillKV(0, kbase, D_);
    fillKV(1, kbase + (long)64 * D_, D_);
    cp_wait<2>();
    __syncthreads();

    unsigned qh[4][4], ql[4][4];
    #pragma unroll
    for (int ks = 0; ks < 4; ks++) {
        const uint32_t aoff =
            ((warp_m * 16 + (lane & 15)) * LDSF + ks * 16 + ((lane >> 4) << 3)) * 2;
        ldsm4(qh[ks], sbase + aoff);
        ldsm4(ql[ks], sbase + FQ_L * 2 + aoff);
    }

    // ---- phase 1: scores (3-pass) ----
    float sf[9][4][4];
    #pragma unroll
    for (int c = 0; c < 9; c++)
        #pragma unroll
        for (int f = 0; f < 4; f++)
            #pragma unroll
            for (int r = 0; r < 4; r++) sf[c][f][r] = 0.f;

    #pragma unroll
    for (int c = 0; c < 9; c++) {
        cp_wait<1>();
        __syncthreads();
        if (c < 7)      fillKV((c + 2) % 3, kbase + (long)(c + 2) * 64 * D_, D_);
        else            fillKV((c + 2) % 3, vbase + (long)(c - 7) * 64, S_);
        const uint32_t baseH = sbase + (FKV0 + (c % 3) * FSTG) * 2;
        const uint32_t baseL = baseH + FQ_L * 2;
        #pragma unroll
        for (int ks = 0; ks < 4; ks++) {
            unsigned kh[2][4], kl[2][4];
            #pragma unroll
            for (int np = 0; np < 2; np++) {
                const uint32_t boff =
                    ((warp_n * 32 + np * 16 + ((lane >> 4) & 1) * 8 + (lane & 7)) * LDSF
                     + ks * 16 + ((lane >> 3) & 1) * 8) * 2;
                ldsm4(kh[np], baseH + boff);
                ldsm4(kl[np], baseL + boff);
            }
            #pragma unroll
            for (int f = 0; f < 4; f++) {
                const unsigned* BH = &kh[f >> 1][(f & 1) * 2];
                const unsigned* BL = &kl[f >> 1][(f & 1) * 2];
                mma16816(sf[c][f], qh[ks], BH);
                mma16816(sf[c][f], qh[ks], BL);
                mma16816(sf[c][f], ql[ks], BH);
            }
        }
    }

    // ---- phase 2: softmax ----
    const int r1 = warp_m * 16 + (lane >> 2), r2 = r1 + 8;
    float m1 = -INFINITY, m2 = -INFINITY;
    #pragma unroll
    for (int c = 0; c < 9; c++)
        #pragma unroll
        for (int f = 0; f < 4; f++) {
            m1 = fmaxf(m1, fmaxf(sf[c][f][0], sf[c][f][1]));
            m2 = fmaxf(m2, fmaxf(sf[c][f][2], sf[c][f][3]));
        }
    #pragma unroll
    for (int o = 1; o <= 2; o <<= 1) {
        m1 = fmaxf(m1, __shfl_xor_sync(0xffffffffu, m1, o));
        m2 = fmaxf(m2, __shfl_xor_sync(0xffffffffu, m2, o));
    }
    if ((lane & 3) == 0) { s_mx[warp_n][r1] = m1; s_mx[warp_n][r2] = m2; }
    __syncthreads();
    m1 = fmaxf(s_mx[0][r1], s_mx[1][r1]);
    m2 = fmaxf(s_mx[0][r2], s_mx[1][r2]);

    float s1 = 0.f, s2 = 0.f;
    #pragma unroll
    for (int c = 0; c < 9; c++)
        #pragma unroll
        for (int f = 0; f < 4; f++) {
            sf[c][f][0] = __expf(sf[c][f][0] - m1);
            sf[c][f][1] = __expf(sf[c][f][1] - m1);
            sf[c][f][2] = __expf(sf[c][f][2] - m2);
            sf[c][f][3] = __expf(sf[c][f][3] - m2);
            s1 += sf[c][f][0] + sf[c][f][1];
            s2 += sf[c][f][2] + sf[c][f][3];
        }
    #pragma unroll
    for (int o = 1; o <= 2; o <<= 1) {
        s1 += __shfl_xor_sync(0xffffffffu, s1, o);
        s2 += __shfl_xor_sync(0xffffffffu, s2, o);
    }
    if ((lane & 3) == 0) { s_sm[warp_n][r1] = s1; s_sm[warp_n][r2] = s2; }
    __syncthreads();
    const float inv1 = 1.f / (s_sm[0][r1] + s_sm[1][r1]);
    const float inv2 = 1.f / (s_sm[0][r2] + s_sm[1][r2]);

    // ---- phase 3: normalize + write attn ----
    #pragma unroll
    for (int c = 0; c < 9; c++)
        #pragma unroll
        for (int f = 0; f < 4; f++) {
            sf[c][f][0] *= inv1; sf[c][f][1] *= inv1;
            sf[c][f][2] *= inv2; sf[c][f][3] *= inv2;
            const int col = c * 64 + warp_n * 32 + f * 8 + (lane & 3) * 2;
            *(float2*)(attnz + (long)(bm + r1) * S_ + col) = make_float2(sf[c][f][0], sf[c][f][1]);
            *(float2*)(attnz + (long)(bm + r2) * S_ + col) = make_float2(sf[c][f][2], sf[c][f][3]);
        }

    // ---- phase 4: PV (2-pass: Ph*Vh + Ph*Vl) ----
    float dacc[8][4];
    #pragma unroll
    for (int f = 0; f < 8; f++)
        #pragma unroll
        for (int r = 0; r < 4; r++) dacc[f][r] = 0.f;

    #pragma unroll
    for (int c = 0; c < 9; c++) {
        cp_wait<1>();
        __syncthreads();
        if (c < 7) fillKV((c + 2) % 3, vbase + (long)(c + 2) * 64, S_);
        else       CP_COMMIT();
        const uint32_t baseH = sbase + (FKV0 + (c % 3) * FSTG) * 2;
        const uint32_t baseL = baseH + FQ_L * 2;
        #pragma unroll
        for (int g = 0; g < 2; g++) {
            unsigned ph[4];
            {
                const float* f0 = sf[c][g * 2];
                const float* f1 = sf[c][g * 2 + 1];
                ph[0] = ph2(f0[0], f0[1]); ph[1] = ph2(f0[2], f0[3]);
                ph[2] = ph2(f1[0], f1[1]); ph[3] = ph2(f1[2], f1[3]);
            }
            const int ksv = warp_n * 2 + g;
            unsigned vh[4][4], vl[4][4];
            #pragma unroll
            for (int np = 0; np < 4; np++) {
                const uint32_t boff =
                    ((np * 16 + ((lane >> 4) & 1) * 8 + (lane & 7)) * LDSF
                     + ksv * 16 + ((lane >> 3) & 1) * 8) * 2;
                ldsm4(vh[np], baseH + boff);
                ldsm4(vl[np], baseL + boff);
            }
            #pragma unroll
            for (int f = 0; f < 8; f++) {
                mma16816(dacc[f], ph, &vh[f >> 1][(f & 1) * 2]);
                mma16816(dacc[f], ph, &vl[f >> 1][(f & 1) * 2]);
            }
        }
    }

    // ---- phase 5: cross-warp_n reduction + ctx write ----
    __syncthreads();
    float* sred = (float*)smem;
    if (warp_n == 0) {
        #pragma unroll
        for (int f = 0; f < 8; f++)
            #pragma unroll
            for (int rr = 0; rr < 2; rr++) {
                const int row = warp_m * 16 + (lane >> 2) + rr * 8;
                const int col = f * 8 + (lane & 3) * 2;
                sred[row * 68 + col]     = dacc[f][rr * 2];
                sred[row * 68 + col + 1] = dacc[f][rr * 2 + 1];
            }
    }
    __syncthreads();
    if (warp_n == 1) {
        const int b = z / H_, h = z % H_;
        #pragma unroll
        for (int f = 0; f < 8; f++)
            #pragma unroll
            for (int rr = 0; rr < 2; rr++) {
                const int row = warp_m * 16 + (lane >> 2) + rr * 8;
                const int col = f * 8 + (lane & 3) * 2;
                const float v0 = dacc[f][rr * 2]     + sred[row * 68 + col];
                const float v1 = dacc[f][rr * 2 + 1] + sred[row * 68 + col + 1];
                *(unsigned*)(ctx + ((long)(b * S_ + bm + row)) * E_ + h * D_ + col) = ph2(v0, v1);
            }
    }
}

// ============================================================================
// Launch
// ============================================================================
extern "C" void kernel_launch(void* const* d_in, const int* in_sizes, int n_in,
                              void* d_out, int out_size)
{
    const float* hs = (const float*)d_in[0];
    const float* qw = (const float*)d_in[1];
    const float* qb = (const float*)d_in[2];
    const float* kw = (const float*)d_in[3];
    const float* kb = (const float*)d_in[4];
    const float* vw = (const float*)d_in[5];
    const float* vb = (const float*)d_in[6];
    const float* ow = (const float*)d_in[7];
    const float* ob = (const float*)d_in[8];
    float* out = (float*)d_out;

    __half *hsP, *qwP, *kwP, *vwP, *owP, *qP, *kP, *vP, *ctxP;
    float* attn_fb;
    cudaGetSymbolAddress((void**)&hsP, g_hs);
    cudaGetSymbolAddress((void**)&qwP, g_qw);
    cudaGetSymbolAddress((void**)&kwP, g_kw);
    cudaGetSymbolAddress((void**)&vwP, g_vw);
    cudaGetSymbolAddress((void**)&owP, g_ow);
    cudaGetSymbolAddress((void**)&qP,  g_q);
    cudaGetSymbolAddress((void**)&kP,  g_k);
    cudaGetSymbolAddress((void**)&vP,  g_v);
    cudaGetSymbolAddress((void**)&ctxP, g_ctx);
    cudaGetSymbolAddress((void**)&attn_fb, g_attn);
    float* attn = ((long)out_size >= OUT1 + NATTN) ? (out + OUT1) : attn_fb;

    cudaFuncSetAttribute(proj_qkv,   cudaFuncAttributeMaxDynamicSharedMemorySize, PSMEM);
    cudaFuncSetAttribute(proj_o,     cudaFuncAttributeMaxDynamicSharedMemorySize, PSMEM);
    cudaFuncSetAttribute(attn_fused, cudaFuncAttributeMaxDynamicSharedMemorySize, FSMEM);

    // 0. pack inputs
    pack_one<<<1024, 256>>>(hs, hsP, MPL);
    pack_two<<<288, 256>>>(qw, qwP, WPL);
    pack_two<<<288, 256>>>(kw, kwP, WPL);
    pack_two<<<288, 256>>>(vw, vwP, WPL);
    pack_two<<<288, 256>>>(ow, owP, WPL);

    // 1. fused QKV projections (2-pass, 128x128 tiles)
    dim3 gproj(E_ / 128, BS_ / 128, 3);
    proj_qkv<<<gproj, 256, PSMEM>>>(hsP, qwP, kwP, vwP, qb, kb, vb, qP, kP, vP);

    // 2. fused scores + softmax + attn write + PV
    dim3 gf(S_ / 64, B_ * H_, 1);
    attn_fused<<<gf, 256, FSMEM>>>(qP, kP, vP, attn, ctxP);

    // 3. output projection (2-pass, 128x128 tiles)
    dim3 go(E_ / 128, BS_ / 128, 1);
    proj_o<<<go, 256, PSMEM>>>(ctxP, owP, ob, out);
}